// round 2
// baseline (speedup 1.0000x reference)
#include <cuda_runtime.h>
#include <cuda_bf16.h>
#include <math.h>

#define N_NODES 100000
#define N_EDGES 3200000
#define D_IN    128
#define D_HID   16
#define D_OUT   2

// ---------------- scratch (device globals: no allocation allowed) ----------------
__device__ float g_h1  [N_NODES * D_HID];   // x @ W1
__device__ float g_agg1[N_NODES * D_HID];   // edge-aggregated layer1
__device__ float g_g2  [N_NODES * D_OUT];   // relu(h1agg) @ W2
__device__ float g_agg2[N_NODES * D_OUT];   // edge-aggregated layer2
__device__ int   g_deg [N_NODES];           // in-degree incl self loop
__device__ float g_dinv[N_NODES];           // rsqrt(deg)

// ---------------- init: zero accumulators, deg=1 (self loop) ----------------
__global__ void init_kernel() {
    int i = blockIdx.x * blockDim.x + threadIdx.x;
    if (i < N_NODES * D_HID) g_agg1[i] = 0.0f;
    if (i < N_NODES * D_OUT) g_agg2[i] = 0.0f;
    if (i < N_NODES)         g_deg[i]  = 1;
}

// ---------------- degree: one thread per edge ----------------
__global__ void deg_kernel(const int* __restrict__ ei) {
    int e = blockIdx.x * blockDim.x + threadIdx.x;
    if (e >= N_EDGES) return;
    int d = ei[N_EDGES + e];   // dst row
    atomicAdd(&g_deg[d], 1);
}

__global__ void dinv_kernel() {
    int i = blockIdx.x * blockDim.x + threadIdx.x;
    if (i < N_NODES) g_dinv[i] = rsqrtf((float)g_deg[i]);
}

// ---------------- GEMM1: h1 = x @ W1  (128 -> 16) ----------------
// Block: 256 threads, 64 nodes per block. x tile staged via shared (coalesced),
// W1 (8KB) in shared. Thread (t) computes node t/4, output cols (t%4)*4 .. +3.
__global__ void gemm1_kernel(const float* __restrict__ x,
                             const float* __restrict__ W1) {
    __shared__ float sW[D_IN * D_HID];       // 8 KB
    __shared__ float sX[64][D_IN + 1];       // padded rows: conflict-free
    const int t = threadIdx.x;
    for (int i = t; i < D_IN * D_HID; i += 256) sW[i] = W1[i];

    const int node0 = blockIdx.x * 64;
    const float4* x4 = (const float4*)(x + (size_t)node0 * D_IN);
    // 64 rows * 32 float4 = 2048 float4, 8 per thread, coalesced
    for (int i = t; i < 64 * 32; i += 256) {
        int r = i >> 5, c = i & 31;
        float4 v = make_float4(0.f, 0.f, 0.f, 0.f);
        if (node0 + r < N_NODES) v = x4[(size_t)r * 32 + c];
        sX[r][c * 4 + 0] = v.x;
        sX[r][c * 4 + 1] = v.y;
        sX[r][c * 4 + 2] = v.z;
        sX[r][c * 4 + 3] = v.w;
    }
    __syncthreads();

    const int node = node0 + (t >> 2);
    const int jb   = (t & 3) * 4;
    const float* xr = sX[t >> 2];
    float a0 = 0.f, a1 = 0.f, a2 = 0.f, a3 = 0.f;
#pragma unroll 16
    for (int k = 0; k < D_IN; k++) {
        float xv = xr[k];
        const float* w = &sW[k * D_HID + jb];
        a0 = fmaf(xv, w[0], a0);
        a1 = fmaf(xv, w[1], a1);
        a2 = fmaf(xv, w[2], a2);
        a3 = fmaf(xv, w[3], a3);
    }
    if (node < N_NODES) {
        float4 o = make_float4(a0, a1, a2, a3);
        *(float4*)&g_h1[(size_t)node * D_HID + jb] = o;
    }
}

// ---------------- layer-1 aggregation: one thread per edge ----------------
__device__ __forceinline__ void red_v4(float* p, float a, float b, float c, float d) {
    asm volatile("red.global.add.v4.f32 [%0], {%1,%2,%3,%4};"
                 :: "l"(p), "f"(a), "f"(b), "f"(c), "f"(d) : "memory");
}
__device__ __forceinline__ void red_v2(float* p, float a, float b) {
    asm volatile("red.global.add.v2.f32 [%0], {%1,%2};"
                 :: "l"(p), "f"(a), "f"(b) : "memory");
}

__global__ void agg1_kernel(const int* __restrict__ ei) {
    int e = blockIdx.x * blockDim.x + threadIdx.x;
    if (e >= N_EDGES) return;
    int s = ei[e];
    int d = ei[N_EDGES + e];
    float c = g_dinv[s] * g_dinv[d];
    const float4* h = (const float4*)&g_h1[(size_t)s * D_HID];
    float* out = &g_agg1[(size_t)d * D_HID];
#pragma unroll
    for (int i = 0; i < 4; i++) {
        float4 v = h[i];
        red_v4(out + i * 4, v.x * c, v.y * c, v.z * c, v.w * c);
    }
}

// ------- fused: h2 = relu(agg1 + self + b1); g2 = h2 @ W2 -------
__global__ void layer2_pre_kernel(const float* __restrict__ b1,
                                  const float* __restrict__ W2) {
    int i = blockIdx.x * blockDim.x + threadIdx.x;
    if (i >= N_NODES) return;
    float di   = g_dinv[i];
    float self = di * di;
    float z0 = 0.f, z1 = 0.f;
#pragma unroll
    for (int j = 0; j < D_HID; j++) {
        float h2 = g_agg1[(size_t)i * D_HID + j]
                 + g_h1[(size_t)i * D_HID + j] * self + b1[j];
        h2 = fmaxf(h2, 0.f);
        z0 = fmaf(h2, W2[j * D_OUT + 0], z0);
        z1 = fmaf(h2, W2[j * D_OUT + 1], z1);
    }
    g_g2[i * 2 + 0] = z0;
    g_g2[i * 2 + 1] = z1;
}

// ---------------- layer-2 aggregation: one thread per edge ----------------
__global__ void agg2_kernel(const int* __restrict__ ei) {
    int e = blockIdx.x * blockDim.x + threadIdx.x;
    if (e >= N_EDGES) return;
    int s = ei[e];
    int d = ei[N_EDGES + e];
    float c = g_dinv[s] * g_dinv[d];
    float m0 = g_g2[s * 2 + 0] * c;
    float m1 = g_g2[s * 2 + 1] * c;
    red_v2(&g_agg2[d * 2], m0, m1);
}

// ---------------- final: add self loop + b2, log_softmax ----------------
__global__ void final_kernel(const float* __restrict__ b2,
                             float* __restrict__ out) {
    int i = blockIdx.x * blockDim.x + threadIdx.x;
    if (i >= N_NODES) return;
    float di   = g_dinv[i];
    float self = di * di;
    float z0 = g_agg2[i * 2 + 0] + g_g2[i * 2 + 0] * self + b2[0];
    float z1 = g_agg2[i * 2 + 1] + g_g2[i * 2 + 1] * self + b2[1];
    float m  = fmaxf(z0, z1);
    float lse = m + logf(expf(z0 - m) + expf(z1 - m));
    out[i * 2 + 0] = z0 - lse;
    out[i * 2 + 1] = z1 - lse;
}

// ---------------- launch ----------------
extern "C" void kernel_launch(void* const* d_in, const int* in_sizes, int n_in,
                              void* d_out, int out_size) {
    const float* x  = (const float*)d_in[0];
    const float* W1 = (const float*)d_in[1];
    const float* b1 = (const float*)d_in[2];
    const float* W2 = (const float*)d_in[3];
    const float* b2 = (const float*)d_in[4];
    const int*   ei = (const int*)d_in[5];
    float* out = (float*)d_out;

    const int T = 256;
    init_kernel<<<(N_NODES * D_HID + T - 1) / T, T>>>();
    deg_kernel<<<(N_EDGES + T - 1) / T, T>>>(ei);
    dinv_kernel<<<(N_NODES + T - 1) / T, T>>>();
    gemm1_kernel<<<(N_NODES + 63) / 64, 256>>>(x, W1);
    agg1_kernel<<<(N_EDGES + T - 1) / T, T>>>(ei);
    layer2_pre_kernel<<<(N_NODES + T - 1) / T, T>>>(b1, W2);
    agg2_kernel<<<(N_EDGES + T - 1) / T, T>>>(ei);
    final_kernel<<<(N_NODES + T - 1) / T, T>>>(b2, out);
}

// round 3
// speedup vs baseline: 1.3617x; 1.3617x over previous
#include <cuda_runtime.h>
#include <cuda_bf16.h>
#include <math.h>

#define N_NODES 100000
#define N_EDGES 3200000
#define D_IN    128
#define D_HID   16
#define D_OUT   2

// ---------------- scratch (device globals) ----------------
__device__ float g_h1  [N_NODES * D_HID];   // (x @ W1) * dinv[node]   (pre-scaled)
__device__ float g_agg1[N_NODES * D_HID];   // sum over in-edges of g_h1[src]
__device__ float g_g2  [N_NODES * D_OUT];   // (h2 @ W2) * dinv[node]  (pre-scaled)
__device__ float g_agg2[N_NODES * D_OUT];   // sum over in-edges of g_g2[src]
__device__ int   g_deg [N_NODES];           // in-degree incl self loop
__device__ float g_dinv[N_NODES];           // rsqrt(deg)

// ---------------- init: zero accumulators, deg=1 (self loop) ----------------
__global__ void init_kernel() {
    int i = blockIdx.x * blockDim.x + threadIdx.x;
    if (i < N_NODES * D_HID) g_agg1[i] = 0.0f;
    if (i < N_NODES * D_OUT) g_agg2[i] = 0.0f;
    if (i < N_NODES)         g_deg[i]  = 1;
}

// ---------------- degree: one thread per edge ----------------
__global__ void deg_kernel(const int* __restrict__ ei) {
    int e = blockIdx.x * blockDim.x + threadIdx.x;
    if (e >= N_EDGES) return;
    atomicAdd(&g_deg[ei[N_EDGES + e]], 1);   // result unused -> RED
}

__global__ void dinv_kernel() {
    int i = blockIdx.x * blockDim.x + threadIdx.x;
    if (i < N_NODES) g_dinv[i] = rsqrtf((float)g_deg[i]);
}

// ---------------- GEMM1: h1 = (x @ W1) * dinv  (128 -> 16) ----------------
// One thread per node. x row read directly from global via float4 (L1 lines
// fully consumed across the k loop); W1 in shared, broadcast reads.
__global__ void __launch_bounds__(256) gemm1_kernel(const float* __restrict__ x,
                                                    const float* __restrict__ W1) {
    __shared__ float4 sW[D_IN * 4];          // W1 rows as 4x float4
    const int t = threadIdx.x;
    for (int i = t; i < D_IN * 4; i += 256) sW[i] = ((const float4*)W1)[i];
    __syncthreads();

    const int node = blockIdx.x * 256 + t;
    if (node >= N_NODES) return;
    const float di = g_dinv[node];
    const float4* xr = (const float4*)(x + (size_t)node * D_IN);

    float acc[D_HID];
#pragma unroll
    for (int j = 0; j < D_HID; j++) acc[j] = 0.0f;

#pragma unroll 4
    for (int k4 = 0; k4 < D_IN / 4; k4++) {
        float4 xv = xr[k4];
        float xs[4] = {xv.x, xv.y, xv.z, xv.w};
#pragma unroll
        for (int kk = 0; kk < 4; kk++) {
            const float4* wrow = &sW[(k4 * 4 + kk) * 4];
#pragma unroll
            for (int j4 = 0; j4 < 4; j4++) {
                float4 w = wrow[j4];
                acc[j4 * 4 + 0] = fmaf(xs[kk], w.x, acc[j4 * 4 + 0]);
                acc[j4 * 4 + 1] = fmaf(xs[kk], w.y, acc[j4 * 4 + 1]);
                acc[j4 * 4 + 2] = fmaf(xs[kk], w.z, acc[j4 * 4 + 2]);
                acc[j4 * 4 + 3] = fmaf(xs[kk], w.w, acc[j4 * 4 + 3]);
            }
        }
    }

    float4* out = (float4*)&g_h1[(size_t)node * D_HID];
#pragma unroll
    for (int j4 = 0; j4 < 4; j4++)
        out[j4] = make_float4(acc[j4 * 4 + 0] * di, acc[j4 * 4 + 1] * di,
                              acc[j4 * 4 + 2] * di, acc[j4 * 4 + 3] * di);
}

// ---------------- vector reductions ----------------
__device__ __forceinline__ void red_v4(float* p, float4 v) {
    asm volatile("red.global.add.v4.f32 [%0], {%1,%2,%3,%4};"
                 :: "l"(p), "f"(v.x), "f"(v.y), "f"(v.z), "f"(v.w) : "memory");
}
__device__ __forceinline__ void red_v2(float* p, float a, float b) {
    asm volatile("red.global.add.v2.f32 [%0], {%1,%2};"
                 :: "l"(p), "f"(a), "f"(b) : "memory");
}

// ---------------- layer-1 aggregation: pure gather + RED ----------------
__global__ void agg1_kernel(const int* __restrict__ ei) {
    int e = blockIdx.x * blockDim.x + threadIdx.x;
    if (e >= N_EDGES) return;
    int s = ei[e];
    int d = ei[N_EDGES + e];
    const float4* h = (const float4*)&g_h1[(size_t)s * D_HID];
    float* out = &g_agg1[(size_t)d * D_HID];
    float4 v0 = h[0], v1 = h[1], v2 = h[2], v3 = h[3];
    red_v4(out +  0, v0);
    red_v4(out +  4, v1);
    red_v4(out +  8, v2);
    red_v4(out + 12, v3);
}

// ------- fused: h2 = relu(dinv*(agg1 + h1p) + b1); g2p = (h2 @ W2)*dinv -------
__global__ void layer2_pre_kernel(const float* __restrict__ b1,
                                  const float* __restrict__ W2) {
    int i = blockIdx.x * blockDim.x + threadIdx.x;
    if (i >= N_NODES) return;
    float di = g_dinv[i];
    float z0 = 0.f, z1 = 0.f;
    const float4* a4 = (const float4*)&g_agg1[(size_t)i * D_HID];
    const float4* h4 = (const float4*)&g_h1[(size_t)i * D_HID];
#pragma unroll
    for (int j4 = 0; j4 < 4; j4++) {
        float4 a = a4[j4];
        float4 h = h4[j4];
        float hv[4] = {a.x + h.x, a.y + h.y, a.z + h.z, a.w + h.w};
#pragma unroll
        for (int k = 0; k < 4; k++) {
            int j = j4 * 4 + k;
            float h2 = fmaxf(fmaf(di, hv[k], b1[j]), 0.f);
            z0 = fmaf(h2, W2[j * D_OUT + 0], z0);
            z1 = fmaf(h2, W2[j * D_OUT + 1], z1);
        }
    }
    g_g2[i * 2 + 0] = z0 * di;
    g_g2[i * 2 + 1] = z1 * di;
}

// ---------------- layer-2 aggregation ----------------
__global__ void agg2_kernel(const int* __restrict__ ei) {
    int e = blockIdx.x * blockDim.x + threadIdx.x;
    if (e >= N_EDGES) return;
    int s = ei[e];
    int d = ei[N_EDGES + e];
    float m0 = g_g2[s * 2 + 0];
    float m1 = g_g2[s * 2 + 1];
    red_v2(&g_agg2[d * 2], m0, m1);
}

// ---------------- final: post-scale, bias, log_softmax ----------------
__global__ void final_kernel(const float* __restrict__ b2,
                             float* __restrict__ out) {
    int i = blockIdx.x * blockDim.x + threadIdx.x;
    if (i >= N_NODES) return;
    float di = g_dinv[i];
    float z0 = fmaf(di, g_agg2[i * 2 + 0] + g_g2[i * 2 + 0], b2[0]);
    float z1 = fmaf(di, g_agg2[i * 2 + 1] + g_g2[i * 2 + 1], b2[1]);
    float m  = fmaxf(z0, z1);
    float lse = m + logf(expf(z0 - m) + expf(z1 - m));
    out[i * 2 + 0] = z0 - lse;
    out[i * 2 + 1] = z1 - lse;
}

// ---------------- launch ----------------
extern "C" void kernel_launch(void* const* d_in, const int* in_sizes, int n_in,
                              void* d_out, int out_size) {
    const float* x  = (const float*)d_in[0];
    const float* W1 = (const float*)d_in[1];
    const float* b1 = (const float*)d_in[2];
    const float* W2 = (const float*)d_in[3];
    const float* b2 = (const float*)d_in[4];
    const int*   ei = (const int*)d_in[5];
    float* out = (float*)d_out;

    const int T = 256;
    init_kernel<<<(N_NODES * D_HID + T - 1) / T, T>>>();
    deg_kernel<<<(N_EDGES + T - 1) / T, T>>>(ei);
    dinv_kernel<<<(N_NODES + T - 1) / T, T>>>();
    gemm1_kernel<<<(N_NODES + 255) / 256, 256>>>(x, W1);
    agg1_kernel<<<(N_EDGES + T - 1) / T, T>>>(ei);
    layer2_pre_kernel<<<(N_NODES + T - 1) / T, T>>>(b1, W2);
    agg2_kernel<<<(N_EDGES + T - 1) / T, T>>>(ei);
    final_kernel<<<(N_NODES + T - 1) / T, T>>>(b2, out);
}

// round 5
// speedup vs baseline: 1.3929x; 1.0229x over previous
#include <cuda_runtime.h>
#include <cuda_fp16.h>
#include <math.h>

#define N_NODES 100000
#define N_EDGES 3200000
#define D_IN    128
#define D_HID   16
#define D_OUT   2

// ---------------- constant weights (copied D2D at launch) ----------------
__constant__ float cW1[D_IN * D_HID];   // 8 KB
__constant__ float cW2[D_HID * D_OUT];
__constant__ float cb1[D_HID];
__constant__ float cb2[D_OUT];

// ---------------- scratch (device globals) ----------------
__device__ float g_h1  [N_NODES * D_HID];   // (x @ W1) * dinv[node]
__device__ float g_agg1[N_NODES * D_HID];   // fp32 edge accumulator
__device__ float g_g2  [N_NODES * D_OUT];   // (h2 @ W2) * dinv[node]
__device__ float g_agg2[N_NODES * D_OUT];
__device__ int   g_deg [N_NODES];
__device__ float g_dinv[N_NODES];

// ---------------- init ----------------
__global__ void init_kernel() {
    int i = blockIdx.x * blockDim.x + threadIdx.x;
    if (i < N_NODES * D_HID) g_agg1[i] = 0.0f;
    if (i < N_NODES * D_OUT) g_agg2[i] = 0.0f;
    if (i < N_NODES)         g_deg[i]  = 1;
}

// ---------------- degree ----------------
__global__ void deg_kernel(const int* __restrict__ ei) {
    int e = blockIdx.x * blockDim.x + threadIdx.x;
    if (e >= N_EDGES) return;
    atomicAdd(&g_deg[ei[N_EDGES + e]], 1);
}

__global__ void dinv_kernel() {
    int i = blockIdx.x * blockDim.x + threadIdx.x;
    if (i < N_NODES) g_dinv[i] = rsqrtf((float)g_deg[i]);
}

// ---------------- GEMM1: h1 = (x @ W1) * dinv ----------------
// One thread per node; W1 from constant memory (uniform port),
// x streamed via float4 LDG. Pure FFMA inner loop.
__global__ void __launch_bounds__(256) gemm1_kernel(const float* __restrict__ x) {
    const int node = blockIdx.x * 256 + threadIdx.x;
    if (node >= N_NODES) return;
    const float4* xr = (const float4*)(x + (size_t)node * D_IN);

    float acc[D_HID];
#pragma unroll
    for (int j = 0; j < D_HID; j++) acc[j] = 0.0f;

#pragma unroll 8
    for (int k4 = 0; k4 < D_IN / 4; k4++) {
        float4 xv = xr[k4];
        float xs[4] = {xv.x, xv.y, xv.z, xv.w};
#pragma unroll
        for (int kk = 0; kk < 4; kk++) {
            const float* w = &cW1[(k4 * 4 + kk) * D_HID];
#pragma unroll
            for (int j = 0; j < D_HID; j++)
                acc[j] = fmaf(xs[kk], w[j], acc[j]);
        }
    }

    const float di = g_dinv[node];
    float4* out = (float4*)&g_h1[(size_t)node * D_HID];
#pragma unroll
    for (int j4 = 0; j4 < 4; j4++)
        out[j4] = make_float4(acc[j4 * 4 + 0] * di, acc[j4 * 4 + 1] * di,
                              acc[j4 * 4 + 2] * di, acc[j4 * 4 + 3] * di);
}

// ---------------- vector reductions ----------------
__device__ __forceinline__ void red_v4(float* p, float4 v) {
    asm volatile("red.global.add.v4.f32 [%0], {%1,%2,%3,%4};"
                 :: "l"(p), "f"(v.x), "f"(v.y), "f"(v.z), "f"(v.w) : "memory");
}
__device__ __forceinline__ void red_v2(float* p, float a, float b) {
    asm volatile("red.global.add.v2.f32 [%0], {%1,%2};"
                 :: "l"(p), "f"(a), "f"(b) : "memory");
}

// ---------------- layer-1 aggregation: pure gather + RED ----------------
__global__ void agg1_kernel(const int* __restrict__ ei) {
    int e = blockIdx.x * blockDim.x + threadIdx.x;
    if (e >= N_EDGES) return;
    int s = ei[e];
    int d = ei[N_EDGES + e];
    const float4* h = (const float4*)&g_h1[(size_t)s * D_HID];
    float* out = &g_agg1[(size_t)d * D_HID];
    float4 v0 = h[0], v1 = h[1], v2 = h[2], v3 = h[3];
    red_v4(out +  0, v0);
    red_v4(out +  4, v1);
    red_v4(out +  8, v2);
    red_v4(out + 12, v3);
}

// ------- fused: h2 = relu(dinv*(agg1 + h1) + b1); g2 = (h2 @ W2)*dinv -------
__global__ void layer2_pre_kernel() {
    int i = blockIdx.x * blockDim.x + threadIdx.x;
    if (i >= N_NODES) return;
    float di = g_dinv[i];
    const float4* a4 = (const float4*)&g_agg1[(size_t)i * D_HID];
    const float4* h4 = (const float4*)&g_h1[(size_t)i * D_HID];
    float z0 = 0.f, z1 = 0.f;
#pragma unroll
    for (int j4 = 0; j4 < 4; j4++) {
        float4 a = a4[j4];
        float4 h = h4[j4];
        float hv[4] = {a.x + h.x, a.y + h.y, a.z + h.z, a.w + h.w};
#pragma unroll
        for (int k = 0; k < 4; k++) {
            int j = j4 * 4 + k;
            float h2 = fmaxf(fmaf(di, hv[k], cb1[j]), 0.f);
            z0 = fmaf(h2, cW2[j * D_OUT + 0], z0);
            z1 = fmaf(h2, cW2[j * D_OUT + 1], z1);
        }
    }
    g_g2[i * 2 + 0] = z0 * di;
    g_g2[i * 2 + 1] = z1 * di;
}

// ---------------- layer-2 aggregation ----------------
__global__ void agg2_kernel(const int* __restrict__ ei) {
    int e = blockIdx.x * blockDim.x + threadIdx.x;
    if (e >= N_EDGES) return;
    int s = ei[e];
    int d = ei[N_EDGES + e];
    float2 m = *(const float2*)&g_g2[s * 2];
    red_v2(&g_agg2[d * 2], m.x, m.y);
}

// ---------------- final: post-scale, bias, log_softmax ----------------
__global__ void final_kernel(float* __restrict__ out) {
    int i = blockIdx.x * blockDim.x + threadIdx.x;
    if (i >= N_NODES) return;
    float di = g_dinv[i];
    float z0 = fmaf(di, g_agg2[i * 2 + 0] + g_g2[i * 2 + 0], cb2[0]);
    float z1 = fmaf(di, g_agg2[i * 2 + 1] + g_g2[i * 2 + 1], cb2[1]);
    float m  = fmaxf(z0, z1);
    float lse = m + logf(expf(z0 - m) + expf(z1 - m));
    out[i * 2 + 0] = z0 - lse;
    out[i * 2 + 1] = z1 - lse;
}

// ---------------- launch ----------------
extern "C" void kernel_launch(void* const* d_in, const int* in_sizes, int n_in,
                              void* d_out, int out_size) {
    const float* x  = (const float*)d_in[0];
    const float* W1 = (const float*)d_in[1];
    const float* b1 = (const float*)d_in[2];
    const float* W2 = (const float*)d_in[3];
    const float* b2 = (const float*)d_in[4];
    const int*   ei = (const int*)d_in[5];
    float* out = (float*)d_out;

    cudaMemcpyToSymbolAsync(cW1, W1, D_IN * D_HID * sizeof(float), 0, cudaMemcpyDeviceToDevice);
    cudaMemcpyToSymbolAsync(cW2, W2, D_HID * D_OUT * sizeof(float), 0, cudaMemcpyDeviceToDevice);
    cudaMemcpyToSymbolAsync(cb1, b1, D_HID * sizeof(float), 0, cudaMemcpyDeviceToDevice);
    cudaMemcpyToSymbolAsync(cb2, b2, D_OUT * sizeof(float), 0, cudaMemcpyDeviceToDevice);

    const int T = 256;
    init_kernel<<<(N_NODES * D_HID + T - 1) / T, T>>>();
    deg_kernel<<<(N_EDGES + T - 1) / T, T>>>(ei);
    dinv_kernel<<<(N_NODES + T - 1) / T, T>>>();
    gemm1_kernel<<<(N_NODES + 255) / 256, 256>>>(x);
    agg1_kernel<<<(N_EDGES + T - 1) / T, T>>>(ei);
    layer2_pre_kernel<<<(N_NODES + T - 1) / T, T>>>();
    agg2_kernel<<<(N_EDGES + T - 1) / T, T>>>(ei);
    final_kernel<<<(N_NODES + T - 1) / T, T>>>(out);
}